// round 15
// baseline (speedup 1.0000x reference)
#include <cuda_runtime.h>
#include <cuda_bf16.h>
#include <cstdint>
#include <stdint.h>

#define NN 100000
#define NE 600000
#define DI 128
#define DH 128
#define NC 64
#define NBLK 98          // ceil(NN/1024)

// Scratch (device globals -- referenced ONLY inside kernels, never from host)
__device__ __align__(16) float g_p[(size_t)NN * NC];      // h1 @ Wn2 (pre-projected)
__device__ float g_deg[NN];                               // in-degree (float)
// CSR (rebuilt every call)
__device__ int g_cnt[NN];
__device__ int g_rowptr[NN];
__device__ int g_cursor[NN];
__device__ int g_eidx[NE];
__device__ int g_blksum[128];
// h1 stored directly as bf16 hi/lo (written by gemm1 epilogue)
__device__ __align__(16) __nv_bfloat16 g_h1hi[(size_t)NN * DH];
__device__ __align__(16) __nv_bfloat16 g_h1lo[(size_t)NN * DH];
// Pre-converted layer-1 weights, B[n][k] = W[k][n], bf16 hi/lo, [ph][128n][128k]
__device__ __align__(16) __nv_bfloat16 g_B1hi[2 * 128 * 128];
__device__ __align__(16) __nv_bfloat16 g_B1lo[2 * 128 * 128];
// Pre-converted layer-2 weights: B2[n][k]; n<64 -> Ws2 col n, n>=64 -> Wn2 col n-64
__device__ __align__(16) __nv_bfloat16 g_B2hi[128 * 128];
__device__ __align__(16) __nv_bfloat16 g_B2lo[128 * 128];

// ---------------- HMMA helpers (baseline PTX, sm_80+, no 'a' target) ----
__device__ __forceinline__ uint32_t smem_to_u32(const void* p) {
    uint32_t a;
    asm("{ .reg .u64 t; cvta.to.shared.u64 t, %1; cvt.u32.u64 %0, t; }" : "=r"(a) : "l"(p));
    return a;
}
__device__ __forceinline__ void ldsm_x4(uint32_t* r, uint32_t addr) {
    asm volatile("ldmatrix.sync.aligned.m8n8.x4.shared.b16 {%0,%1,%2,%3}, [%4];"
                 : "=r"(r[0]), "=r"(r[1]), "=r"(r[2]), "=r"(r[3]) : "r"(addr));
}
__device__ __forceinline__ void mma_bf16(float* d, const uint32_t* a, const uint32_t* b) {
    asm volatile("mma.sync.aligned.m16n8k16.row.col.f32.bf16.bf16.f32 "
                 "{%0,%1,%2,%3}, {%4,%5,%6,%7}, {%8,%9}, {%0,%1,%2,%3};"
                 : "+f"(d[0]), "+f"(d[1]), "+f"(d[2]), "+f"(d[3])
                 : "r"(a[0]), "r"(a[1]), "r"(a[2]), "r"(a[3]), "r"(b[0]), "r"(b[1]));
}
__device__ __forceinline__ void cp_async16(uint32_t saddr, const void* g, int szbytes) {
    asm volatile("cp.async.cg.shared.global [%0], [%1], 16, %2;"
                 :: "r"(saddr), "l"(g), "r"(szbytes));
}
#define CP_COMMIT() asm volatile("cp.async.commit_group;" ::: "memory")
#define CP_WAIT0()  asm volatile("cp.async.wait_group 0;" ::: "memory")

// SMEM maps: rows padded to 136 bf16 (272B) -> conflict-free ldsm
#define RSTR 272
#define TILE_B (128 * RSTR)
// gemm1: A_hi, A_lo, then 4 B tiles [ph][hi/lo]
#define SM_A_HI 0
#define SM_A_LO TILE_B
#define SM_B    (2 * TILE_B)
#define SMEM_MMA (6 * TILE_B)      // 208896 B
// gemm2: A0hi, A0lo, A1hi, A1lo, B_hi, B_lo
#define SM2_B   (4 * TILE_B)
#define SMEM_MMA2 (6 * TILE_B)     // 208896 B

// ================= setup: zero cnt + convert weights =================
__global__ void setup_kernel(const float* __restrict__ Ws1, const float* __restrict__ Wn1,
                             const float* __restrict__ Ws2, const float* __restrict__ Wn2) {
    int i = blockIdx.x * blockDim.x + threadIdx.x;
    if (i < 32768) {                       // W1: [ph][n][k]
        int ph = i >> 14, rem = i & 16383;
        int n = rem >> 7, k = rem & 127;
        const float* W = ph ? Wn1 : Ws1;
        float v = W[k * 128 + n];
        __nv_bfloat16 h = __float2bfloat16(v);
        g_B1hi[i] = h;
        g_B1lo[i] = __float2bfloat16(v - __bfloat162float(h));
    } else if (i < 49152) {                // W2: [n][k], n<64 Ws2 else Wn2
        int j = i - 32768;
        int n = j >> 7, k = j & 127;
        float v = (n < 64) ? Ws2[k * 64 + n] : Wn2[k * 64 + (n - 64)];
        __nv_bfloat16 h = __float2bfloat16(v);
        g_B2hi[j] = h;
        g_B2lo[j] = __float2bfloat16(v - __bfloat162float(h));
    } else if (i < 49152 + NN) {
        g_cnt[i - 49152] = 0;
    }
}

// ================= CSR build (proven R14) =================
__global__ void hist_kernel(const int* __restrict__ dst) {
    int e = blockIdx.x * blockDim.x + threadIdx.x;
    if (e < NE) atomicAdd(&g_cnt[__ldg(dst + e)], 1);
}
__global__ void scan1_kernel() {
    __shared__ int s[1024];
    int t = threadIdx.x;
    int idx = blockIdx.x * 1024 + t;
    int v = (idx < NN) ? g_cnt[idx] : 0;
    s[t] = v;
    __syncthreads();
    for (int off = 1; off < 1024; off <<= 1) {
        int tmp = (t >= off) ? s[t - off] : 0;
        __syncthreads();
        s[t] += tmp;
        __syncthreads();
    }
    if (idx < NN) g_rowptr[idx] = s[t] - v;
    if (t == 1023) g_blksum[blockIdx.x] = s[t];
}
__global__ void scan2_kernel() {
    __shared__ int s[128];
    int t = threadIdx.x;
    int v = (t < NBLK) ? g_blksum[t] : 0;
    s[t] = v;
    __syncthreads();
    for (int off = 1; off < 128; off <<= 1) {
        int tmp = (t >= off) ? s[t - off] : 0;
        __syncthreads();
        s[t] += tmp;
        __syncthreads();
    }
    if (t < NBLK) g_blksum[t] = s[t] - v;
}
__global__ void scan3_kernel() {
    int i = blockIdx.x * blockDim.x + threadIdx.x;
    if (i >= NN) return;
    int rp = g_rowptr[i] + g_blksum[i >> 10];
    g_rowptr[i] = rp;
    g_cursor[i] = rp;
    g_deg[i] = (float)g_cnt[i];
}
__global__ void fill_kernel(const int* __restrict__ src, const int* __restrict__ dst) {
    int e = blockIdx.x * blockDim.x + threadIdx.x;
    if (e < NE) {
        int d = __ldg(dst + e);
        int pos = atomicAdd(&g_cursor[d], 1);
        g_eidx[pos] = __ldg(src + e);
    }
}

// ---------------------------------------------------------------------------
// Layer 1 via HMMA, 512 threads, with phase-1 gather FUSED (no g_nbr1):
//   h1 = relu(x@Ws1 + mean_{in}(x)@Wn1 + b1)  -> g_h1hi/g_h1lo (bf16 split)
// ---------------------------------------------------------------------------
__global__ void __launch_bounds__(512)
gemm1_mma_kernel(const float* __restrict__ x,
                 const float* __restrict__ bias) {
    extern __shared__ char smem[];
    uint32_t smem_base = smem_to_u32(smem);
    int tid = threadIdx.x;
    int w = tid >> 5, l = tid & 31;
    int wm = w & 3, wn = w >> 2;

    {   // preload B tiles ([ph][hi/lo][128n][k])
        const uint32_t* hi32 = (const uint32_t*)g_B1hi;
        const uint32_t* lo32 = (const uint32_t*)g_B1lo;
        for (int i = tid; i < 32768; i += 512) {
            int kp = i & 63, n = (i >> 6) & 127, hilo = (i >> 13) & 1, ph = i >> 14;
            uint32_t v = (hilo ? lo32 : hi32)[ph * 8192 + n * 64 + kp];
            *(uint32_t*)(smem + SM_B + (ph * 2 + hilo) * TILE_B + n * RSTR + kp * 4) = v;
        }
    }

    int rowc = tid >> 2;               // phase-0 loader row
    int c0 = (tid & 3) << 5;           // phase-0 feature quarter

    const int nTiles = (NN + 127) / 128;
    for (int tile = blockIdx.x; tile < nTiles; tile += gridDim.x) {
        int base = tile * 128;
        float acc[2][4][4];
        #pragma unroll
        for (int bm = 0; bm < 2; bm++)
            #pragma unroll
            for (int bn = 0; bn < 4; bn++)
                #pragma unroll
                for (int j = 0; j < 4; j++) acc[bm][bn][j] = 0.f;

        #pragma unroll
        for (int ph = 0; ph < 2; ++ph) {
            __syncthreads();
            if (ph == 0) {
                // A = x tile (proven loader)
                int node = base + rowc;
                bool valid = node < NN;
                const float4* rp = (const float4*)(x + (size_t)node * DI + c0);
                #pragma unroll
                for (int i = 0; i < 8; i++) {
                    float4 v = make_float4(0.f, 0.f, 0.f, 0.f);
                    if (valid) v = rp[i];
                    int c = c0 + i * 4;
                    __nv_bfloat162 h01, l01, h23, l23;
                    h01.x = __float2bfloat16(v.x);
                    l01.x = __float2bfloat16(v.x - __bfloat162float(h01.x));
                    h01.y = __float2bfloat16(v.y);
                    l01.y = __float2bfloat16(v.y - __bfloat162float(h01.y));
                    h23.x = __float2bfloat16(v.z);
                    l23.x = __float2bfloat16(v.z - __bfloat162float(h23.x));
                    h23.y = __float2bfloat16(v.w);
                    l23.y = __float2bfloat16(v.w - __bfloat162float(h23.y));
                    uint32_t o = (uint32_t)(rowc * RSTR + c * 2);
                    *(__nv_bfloat162*)(smem + SM_A_HI + o)     = h01;
                    *(__nv_bfloat162*)(smem + SM_A_HI + o + 4) = h23;
                    *(__nv_bfloat162*)(smem + SM_A_LO + o)     = l01;
                    *(__nv_bfloat162*)(smem + SM_A_LO + o + 4) = l23;
                }
            } else {
                // A = mean of in-neighbors of x (fused gather; warp per row,
                // 8 rows per warp; lane = feature chunk of 4 floats)
                for (int i = 0; i < 8; i++) {
                    int r = (w << 3) + i;
                    int nd = base + r;
                    float4 acc4 = make_float4(0.f, 0.f, 0.f, 0.f);
                    float inv = 1.0f;
                    if (nd < NN) {
                        int beg = __ldg(g_rowptr + nd);
                        int cnt = __ldg(g_cnt + nd);
                        if (cnt > 0) inv = 1.0f / (float)cnt;
                        for (int i0 = 0; i0 < cnt; i0 += 32) {
                            int m = min(32, cnt - i0);
                            int my = (l < m) ? __ldg(g_eidx + beg + i0 + l) : 0;
                            for (int j = 0; j < m; j++) {
                                int sidx = __shfl_sync(0xffffffffu, my, j);
                                float4 v = __ldg((const float4*)x + (size_t)sidx * 32 + l);
                                acc4.x += v.x; acc4.y += v.y;
                                acc4.z += v.z; acc4.w += v.w;
                            }
                        }
                    }
                    acc4.x *= inv; acc4.y *= inv; acc4.z *= inv; acc4.w *= inv;
                    int c = l << 2;
                    __nv_bfloat162 h01, l01, h23, l23;
                    h01.x = __float2bfloat16(acc4.x);
                    l01.x = __float2bfloat16(acc4.x - __bfloat162float(h01.x));
                    h01.y = __float2bfloat16(acc4.y);
                    l01.y = __float2bfloat16(acc4.y - __bfloat162float(h01.y));
                    h23.x = __float2bfloat16(acc4.z);
                    l23.x = __float2bfloat16(acc4.z - __bfloat162float(h23.x));
                    h23.y = __float2bfloat16(acc4.w);
                    l23.y = __float2bfloat16(acc4.w - __bfloat162float(h23.y));
                    uint32_t o = (uint32_t)(r * RSTR + c * 2);
                    *(__nv_bfloat162*)(smem + SM_A_HI + o)     = h01;
                    *(__nv_bfloat162*)(smem + SM_A_HI + o + 4) = h23;
                    *(__nv_bfloat162*)(smem + SM_A_LO + o)     = l01;
                    *(__nv_bfloat162*)(smem + SM_A_LO + o + 4) = l23;
                }
            }
            __syncthreads();

            uint32_t bb_hi = smem_base + SM_B + (uint32_t)(ph * 2) * TILE_B;
            #pragma unroll
            for (int s = 0; s < 8; s++) {
                int k0 = s << 4;
                uint32_t ahi[2][4], alo[2][4];
                #pragma unroll
                for (int bm = 0; bm < 2; bm++) {
                    int row = (wm << 5) + (bm << 4) + (l & 7) + (((l >> 3) & 1) << 3);
                    int col = k0 + ((l >> 4) << 3);
                    uint32_t ad = smem_base + (uint32_t)(row * RSTR + col * 2);
                    ldsm_x4(ahi[bm], ad + SM_A_HI);
                    ldsm_x4(alo[bm], ad + SM_A_LO);
                }
                uint32_t bhi[4][2], blo[4][2];
                #pragma unroll
                for (int t = 0; t < 2; t++) {
                    int row = (wn << 5) + (t << 4) + (l & 7) + ((l >> 4) << 3);
                    int col = k0 + (((l >> 3) & 1) << 3);
                    uint32_t bd = bb_hi + (uint32_t)(row * RSTR + col * 2);
                    uint32_t r[4];
                    ldsm_x4(r, bd);
                    bhi[2 * t][0] = r[0]; bhi[2 * t][1] = r[1];
                    bhi[2 * t + 1][0] = r[2]; bhi[2 * t + 1][1] = r[3];
                    ldsm_x4(r, bd + TILE_B);
                    blo[2 * t][0] = r[0]; blo[2 * t][1] = r[1];
                    blo[2 * t + 1][0] = r[2]; blo[2 * t + 1][1] = r[3];
                }
                #pragma unroll
                for (int bm = 0; bm < 2; bm++)
                    #pragma unroll
                    for (int bn = 0; bn < 4; bn++) {
                        mma_bf16(acc[bm][bn], ahi[bm], bhi[bn]);
                        mma_bf16(acc[bm][bn], ahi[bm], blo[bn]);
                        mma_bf16(acc[bm][bn], alo[bm], bhi[bn]);
                    }
            }
        }

        // Epilogue: bias + relu -> g_h1hi/g_h1lo
        #pragma unroll
        for (int bm = 0; bm < 2; bm++) {
            int r0 = base + (wm << 5) + (bm << 4) + (l >> 2);
            #pragma unroll
            for (int bn = 0; bn < 4; bn++) {
                int n = (wn << 5) + (bn << 3) + ((l & 3) << 1);
                float2 bv = *(const float2*)(bias + n);
                #pragma unroll
                for (int half = 0; half < 2; half++) {
                    int r = r0 + half * 8;
                    if (r < NN) {
                        float o0 = fmaxf(acc[bm][bn][2 * half + 0] + bv.x, 0.f);
                        float o1 = fmaxf(acc[bm][bn][2 * half + 1] + bv.y, 0.f);
                        __nv_bfloat162 h2, l2;
                        h2.x = __float2bfloat16(o0);
                        l2.x = __float2bfloat16(o0 - __bfloat162float(h2.x));
                        h2.y = __float2bfloat16(o1);
                        l2.y = __float2bfloat16(o1 - __bfloat162float(h2.y));
                        *(__nv_bfloat162*)(g_h1hi + (size_t)r * DH + n) = h2;
                        *(__nv_bfloat162*)(g_h1lo + (size_t)r * DH + n) = l2;
                    }
                }
            }
        }
    }
}

// ---------------------------------------------------------------------------
// Layer 2 via HMMA, 512 threads, DOUBLE-BUFFERED A via cp.async:
//   N=128 GEMM, B2 = [Ws2 | Wn2]^T; cols 0-63 (+b2) -> d_out ; 64-127 -> g_p
// ---------------------------------------------------------------------------
__global__ void __launch_bounds__(512)
gemm2_mma_kernel(const float* __restrict__ bias,
                 float* __restrict__ out_ext) {
    extern __shared__ char smem[];
    uint32_t smem_base = smem_to_u32(smem);
    int tid = threadIdx.x;
    int w = tid >> 5, l = tid & 31;
    int wm = w & 3, wn = w >> 2;

    {   // preload B2 hi/lo
        const uint32_t* hi32 = (const uint32_t*)g_B2hi;
        const uint32_t* lo32 = (const uint32_t*)g_B2lo;
        for (int i = tid; i < 16384; i += 512) {
            int kp = i & 63, n = (i >> 6) & 127, hilo = i >> 13;
            uint32_t v = (hilo ? lo32 : hi32)[n * 64 + kp];
            *(uint32_t*)(smem + SM2_B + hilo * TILE_B + n * RSTR + kp * 4) = v;
        }
    }

    int rowc = tid >> 2;               // A-copy row (0..127)
    int jh = (tid & 3) << 4;           // uint32 quarter (16 of 64 per row)

    const int nTiles = (NN + 127) / 128;

    // prefetch helper (macro-free inline)
    auto prefetch = [&](int tile, int p) {
        int node = tile * 128 + rowc;
        int sz = (node < NN) ? 16 : 0;
        const char* rh = (const char*)(g_h1hi + (size_t)node * DH) + jh * 4;
        const char* rl = (const char*)(g_h1lo + (size_t)node * DH) + jh * 4;
        uint32_t ob = smem_base + (uint32_t)(p * 2) * TILE_B
                    + (uint32_t)(rowc * RSTR + jh * 4);
        #pragma unroll
        for (int c = 0; c < 4; c++) {
            cp_async16(ob + c * 16, rh + c * 16, sz);
            cp_async16(ob + TILE_B + c * 16, rl + c * 16, sz);
        }
    };

    int p = 0;
    if (blockIdx.x < nTiles) prefetch(blockIdx.x, 0);
    CP_COMMIT();
    CP_WAIT0();
    __syncthreads();   // buf0 + B ready

    for (int tile = blockIdx.x; tile < nTiles; tile += gridDim.x) {
        int base = tile * 128;
        int nxt = tile + gridDim.x;
        if (nxt < nTiles) prefetch(nxt, p ^ 1);
        CP_COMMIT();

        float acc[2][4][4];
        #pragma unroll
        for (int bm = 0; bm < 2; bm++)
            #pragma unroll
            for (int bn = 0; bn < 4; bn++)
                #pragma unroll
                for (int j = 0; j < 4; j++) acc[bm][bn][j] = 0.f;

        uint32_t a_base = smem_base + (uint32_t)(p * 2) * TILE_B;
        uint32_t bb_hi = smem_base + SM2_B;
        #pragma unroll
        for (int s = 0; s < 8; s++) {
            int k0 = s << 4;
            uint32_t ahi[2][4], alo[2][4];
            #pragma unroll
            for (int bm = 0; bm < 2; bm++) {
                int row = (wm << 5) + (bm << 4) + (l & 7) + (((l >> 3) & 1) << 3);
                int col = k0 + ((l >> 4) << 3);
                uint32_t ad = a_base + (uint32_t)(row * RSTR + col * 2);
                ldsm_x4(ahi[bm], ad);
                ldsm_x4(alo[bm], ad + TILE_B);
            }
            uint32_t bhi[4][2], blo[4][2];
            #pragma unroll
            for (int t = 0; t < 2; t++) {
                int row = (wn << 5) + (t << 4) + (l & 7) + ((l >> 4) << 3);
                int col = k0 + (((l >> 3) & 1) << 3);
                uint32_t bd = bb_hi + (uint32_t)(row * RSTR + col * 2);
                uint32_t r[4];
                ldsm_x4(r, bd);
                bhi[2 * t][0] = r[0]; bhi[2 * t][1] = r[1];
                bhi[2 * t + 1][0] = r[2]; bhi[2 * t + 1][1] = r[3];
                ldsm_x4(r, bd + TILE_B);
                blo[2 * t][0] = r[0]; blo[2 * t][1] = r[1];
                blo[2 * t + 1][0] = r[2]; blo[2 * t + 1][1] = r[3];
            }
            #pragma unroll
            for (int bm = 0; bm < 2; bm++)
                #pragma unroll
                for (int bn = 0; bn < 4; bn++) {
                    mma_bf16(acc[bm][bn], ahi[bm], bhi[bn]);
                    mma_bf16(acc[bm][bn], ahi[bm], blo[bn]);
                    mma_bf16(acc[bm][bn], alo[bm], bhi[bn]);
                }
        }

        // Epilogue
        #pragma unroll
        for (int bm = 0; bm < 2; bm++) {
            int r0 = base + (wm << 5) + (bm << 4) + (l >> 2);
            #pragma unroll
            for (int bn = 0; bn < 4; bn++) {
                int n = (wn << 5) + (bn << 3) + ((l & 3) << 1);
                #pragma unroll
                for (int half = 0; half < 2; half++) {
                    int r = r0 + half * 8;
                    if (r < NN) {
                        float o0 = acc[bm][bn][2 * half + 0];
                        float o1 = acc[bm][bn][2 * half + 1];
                        if (n < 64) {
                            float2 bv = *(const float2*)(bias + n);
                            float2 o = make_float2(o0 + bv.x, o1 + bv.y);
                            *(float2*)(out_ext + (size_t)r * NC + n) = o;
                        } else {
                            float2 o = make_float2(o0, o1);
                            *(float2*)(g_p + (size_t)r * NC + (n - 64)) = o;
                        }
                    }
                }
            }
        }

        CP_WAIT0();
        __syncthreads();
        p ^= 1;
    }
}

// ---------------------------------------------------------------------------
// Layer 2 gather (fused final): half-warp per node, out += (sum g_p[src]) / deg
// ---------------------------------------------------------------------------
__global__ void gather2_kernel(float* __restrict__ out) {
    int gh = (blockIdx.x * blockDim.x + threadIdx.x) >> 4;
    if (gh >= NN) return;
    int l16 = threadIdx.x & 15;
    unsigned mask = 0xFFFFu << (threadIdx.x & 16);
    int beg = __ldg(g_rowptr + gh);
    int cnt = __ldg(g_cnt + gh);
    float4 acc = make_float4(0.f, 0.f, 0.f, 0.f);
    for (int i0 = 0; i0 < cnt; i0 += 16) {
        int m = min(16, cnt - i0);
        int myidx = (l16 < m) ? __ldg(g_eidx + beg + i0 + l16) : 0;
        for (int j = 0; j < m; j++) {
            int s = __shfl_sync(mask, myidx, j, 16);
            float4 v = __ldg((const float4*)g_p + (size_t)s * 16 + l16);
            acc.x += v.x; acc.y += v.y; acc.z += v.z; acc.w += v.w;
        }
    }
    float inv = 1.0f / fmaxf(g_deg[gh], 1.0f);
    float4 o = ((float4*)out)[(size_t)gh * 16 + l16];
    o.x += acc.x * inv; o.y += acc.y * inv;
    o.z += acc.z * inv; o.w += acc.w * inv;
    ((float4*)out)[(size_t)gh * 16 + l16] = o;
}

// ---------------------------------------------------------------------------
extern "C" void kernel_launch(void* const* d_in, const int* in_sizes, int n_in,
                              void* d_out, int out_size) {
    const float* x    = (const float*)d_in[0];
    const int*   src  = (const int*)d_in[1];
    const int*   dst  = (const int*)d_in[2];
    const float* Ws1  = (const float*)d_in[3];
    const float* Wn1  = (const float*)d_in[4];
    const float* b1   = (const float*)d_in[5];
    const float* Ws2  = (const float*)d_in[6];
    const float* Wn2  = (const float*)d_in[7];
    const float* b2   = (const float*)d_in[8];
    float* out = (float*)d_out;

    cudaFuncSetAttribute(gemm1_mma_kernel, cudaFuncAttributeMaxDynamicSharedMemorySize, SMEM_MMA);
    cudaFuncSetAttribute(gemm2_mma_kernel, cudaFuncAttributeMaxDynamicSharedMemorySize, SMEM_MMA2);

    // 1) setup: zero cnt + convert weights (one kernel)
    setup_kernel<<<(49152 + NN + 255) / 256, 256>>>(Ws1, Wn1, Ws2, Wn2);
    // 2) CSR build
    hist_kernel<<<(NE + 255) / 256, 256>>>(dst);
    scan1_kernel<<<NBLK, 1024>>>();
    scan2_kernel<<<1, 128>>>();
    scan3_kernel<<<(NN + 255) / 256, 256>>>();
    fill_kernel<<<(NE + 255) / 256, 256>>>(src, dst);
    // 3) layer-1 GEMM with fused neighbor gather -> g_h1hi/g_h1lo
    gemm1_mma_kernel<<<148, 512, SMEM_MMA>>>(x, b1);
    // 4) layer-2 dual GEMM (double-buffered A): d_out = h1@Ws2 + b2 ; g_p = h1@Wn2
    gemm2_mma_kernel<<<148, 512, SMEM_MMA2>>>(b2, out);
    // 5) gather of g_p fused with final add
    gather2_kernel<<<(NN * 16 + 255) / 256, 256>>>(out);
}

// round 16
// speedup vs baseline: 1.4753x; 1.4753x over previous
#include <cuda_runtime.h>
#include <cuda_bf16.h>
#include <cstdint>
#include <stdint.h>

#define NN 100000
#define NE 600000
#define DI 128
#define DH 128
#define NC 64
#define NBLK 98          // ceil(NN/1024)

// Scratch (device globals -- referenced ONLY inside kernels, never from host)
__device__ __align__(16) float g_nbr1[(size_t)NN * DI];   // layer-1 neighbor sums
__device__ __align__(16) float g_p[(size_t)NN * NC];      // h1 @ Wn2 (pre-projected)
__device__ float g_deg[NN];                               // in-degree (float)
// CSR (rebuilt every call)
__device__ int g_cnt[NN];
__device__ int g_rowptr[NN];
__device__ int g_cursor[NN];
__device__ int g_eidx[NE];
__device__ int g_blksum[128];
// h1 stored directly as bf16 hi/lo (written by gemm1 epilogue)
__device__ __align__(16) __nv_bfloat16 g_h1hi[(size_t)NN * DH];
__device__ __align__(16) __nv_bfloat16 g_h1lo[(size_t)NN * DH];
// Pre-converted layer-1 weights, B[n][k] = W[k][n], bf16 hi/lo, [ph][128n][128k]
__device__ __align__(16) __nv_bfloat16 g_B1hi[2 * 128 * 128];
__device__ __align__(16) __nv_bfloat16 g_B1lo[2 * 128 * 128];
// Pre-converted layer-2 weights: B2[n][k]; n<64 -> Ws2 col n, n>=64 -> Wn2 col n-64
__device__ __align__(16) __nv_bfloat16 g_B2hi[128 * 128];
__device__ __align__(16) __nv_bfloat16 g_B2lo[128 * 128];

// ---------------- HMMA helpers (baseline PTX, sm_80+, no 'a' target) ----
__device__ __forceinline__ uint32_t smem_to_u32(const void* p) {
    uint32_t a;
    asm("{ .reg .u64 t; cvta.to.shared.u64 t, %1; cvt.u32.u64 %0, t; }" : "=r"(a) : "l"(p));
    return a;
}
__device__ __forceinline__ void ldsm_x4(uint32_t* r, uint32_t addr) {
    asm volatile("ldmatrix.sync.aligned.m8n8.x4.shared.b16 {%0,%1,%2,%3}, [%4];"
                 : "=r"(r[0]), "=r"(r[1]), "=r"(r[2]), "=r"(r[3]) : "r"(addr));
}
__device__ __forceinline__ void mma_bf16(float* d, const uint32_t* a, const uint32_t* b) {
    asm volatile("mma.sync.aligned.m16n8k16.row.col.f32.bf16.bf16.f32 "
                 "{%0,%1,%2,%3}, {%4,%5,%6,%7}, {%8,%9}, {%0,%1,%2,%3};"
                 : "+f"(d[0]), "+f"(d[1]), "+f"(d[2]), "+f"(d[3])
                 : "r"(a[0]), "r"(a[1]), "r"(a[2]), "r"(a[3]), "r"(b[0]), "r"(b[1]));
}
__device__ __forceinline__ void cp_async16(uint32_t saddr, const void* g, int szbytes) {
    asm volatile("cp.async.cg.shared.global [%0], [%1], 16, %2;"
                 :: "r"(saddr), "l"(g), "r"(szbytes));
}
#define CP_COMMIT() asm volatile("cp.async.commit_group;" ::: "memory")
#define CP_WAIT0()  asm volatile("cp.async.wait_group 0;" ::: "memory")

// SMEM maps: rows padded to 136 bf16 (272B) -> conflict-free ldsm
#define RSTR 272
#define TILE_B (128 * RSTR)
// gemm1: A_hi, A_lo, then 4 B tiles [ph][hi/lo]
#define SM_A_HI 0
#define SM_A_LO TILE_B
#define SM_B    (2 * TILE_B)
#define SMEM_MMA (6 * TILE_B)      // 208896 B
// gemm2: A0hi, A0lo, A1hi, A1lo, B_hi, B_lo
#define SM2_B   (4 * TILE_B)
#define SMEM_MMA2 (6 * TILE_B)     // 208896 B

// ================= setup: zero cnt + convert weights =================
__global__ void setup_kernel(const float* __restrict__ Ws1, const float* __restrict__ Wn1,
                             const float* __restrict__ Ws2, const float* __restrict__ Wn2) {
    int i = blockIdx.x * blockDim.x + threadIdx.x;
    if (i < 32768) {                       // W1: [ph][n][k]
        int ph = i >> 14, rem = i & 16383;
        int n = rem >> 7, k = rem & 127;
        const float* W = ph ? Wn1 : Ws1;
        float v = W[k * 128 + n];
        __nv_bfloat16 h = __float2bfloat16(v);
        g_B1hi[i] = h;
        g_B1lo[i] = __float2bfloat16(v - __bfloat162float(h));
    } else if (i < 49152) {                // W2: [n][k], n<64 Ws2 else Wn2
        int j = i - 32768;
        int n = j >> 7, k = j & 127;
        float v = (n < 64) ? Ws2[k * 64 + n] : Wn2[k * 64 + (n - 64)];
        __nv_bfloat16 h = __float2bfloat16(v);
        g_B2hi[j] = h;
        g_B2lo[j] = __float2bfloat16(v - __bfloat162float(h));
    } else if (i < 49152 + NN) {
        g_cnt[i - 49152] = 0;
    }
}

// ================= CSR build (proven R14) =================
__global__ void hist_kernel(const int* __restrict__ dst) {
    int e = blockIdx.x * blockDim.x + threadIdx.x;
    if (e < NE) atomicAdd(&g_cnt[__ldg(dst + e)], 1);
}
__global__ void scan1_kernel() {
    __shared__ int s[1024];
    int t = threadIdx.x;
    int idx = blockIdx.x * 1024 + t;
    int v = (idx < NN) ? g_cnt[idx] : 0;
    s[t] = v;
    __syncthreads();
    for (int off = 1; off < 1024; off <<= 1) {
        int tmp = (t >= off) ? s[t - off] : 0;
        __syncthreads();
        s[t] += tmp;
        __syncthreads();
    }
    if (idx < NN) g_rowptr[idx] = s[t] - v;
    if (t == 1023) g_blksum[blockIdx.x] = s[t];
}
__global__ void scan2_kernel() {
    __shared__ int s[128];
    int t = threadIdx.x;
    int v = (t < NBLK) ? g_blksum[t] : 0;
    s[t] = v;
    __syncthreads();
    for (int off = 1; off < 128; off <<= 1) {
        int tmp = (t >= off) ? s[t - off] : 0;
        __syncthreads();
        s[t] += tmp;
        __syncthreads();
    }
    if (t < NBLK) g_blksum[t] = s[t] - v;
}
__global__ void scan3_kernel() {
    int i = blockIdx.x * blockDim.x + threadIdx.x;
    if (i >= NN) return;
    int rp = g_rowptr[i] + g_blksum[i >> 10];
    g_rowptr[i] = rp;
    g_cursor[i] = rp;
    g_deg[i] = (float)g_cnt[i];
}
__global__ void fill_kernel(const int* __restrict__ src, const int* __restrict__ dst) {
    int e = blockIdx.x * blockDim.x + threadIdx.x;
    if (e < NE) {
        int d = __ldg(dst + e);
        int pos = atomicAdd(&g_cursor[d], 1);
        g_eidx[pos] = __ldg(src + e);
    }
}

// ================= Gathers (proven R14) =================
// Layer 1: warp per node, nbr1[node] = sum over in-edges of x[src]
__global__ void gather1_kernel(const float* __restrict__ x) {
    int gw = (blockIdx.x * blockDim.x + threadIdx.x) >> 5;
    if (gw >= NN) return;
    int lane = threadIdx.x & 31;
    int beg = __ldg(g_rowptr + gw);
    int cnt = __ldg(g_cnt + gw);
    float4 acc = make_float4(0.f, 0.f, 0.f, 0.f);
    for (int i0 = 0; i0 < cnt; i0 += 32) {
        int m = min(32, cnt - i0);
        int myidx = (lane < m) ? __ldg(g_eidx + beg + i0 + lane) : 0;
        for (int j = 0; j < m; j++) {
            int s = __shfl_sync(0xffffffffu, myidx, j);
            float4 v = __ldg((const float4*)x + (size_t)s * 32 + lane);
            acc.x += v.x; acc.y += v.y; acc.z += v.z; acc.w += v.w;
        }
    }
    ((float4*)g_nbr1)[(size_t)gw * 32 + lane] = acc;
}

// Layer 2 (fused final): half-warp per node, out[node] += (sum g_p[src]) / deg
__global__ void gather2_kernel(float* __restrict__ out) {
    int gh = (blockIdx.x * blockDim.x + threadIdx.x) >> 4;
    if (gh >= NN) return;
    int l16 = threadIdx.x & 15;
    unsigned mask = 0xFFFFu << (threadIdx.x & 16);
    int beg = __ldg(g_rowptr + gh);
    int cnt = __ldg(g_cnt + gh);
    float4 acc = make_float4(0.f, 0.f, 0.f, 0.f);
    for (int i0 = 0; i0 < cnt; i0 += 16) {
        int m = min(16, cnt - i0);
        int myidx = (l16 < m) ? __ldg(g_eidx + beg + i0 + l16) : 0;
        for (int j = 0; j < m; j++) {
            int s = __shfl_sync(mask, myidx, j, 16);
            float4 v = __ldg((const float4*)g_p + (size_t)s * 16 + l16);
            acc.x += v.x; acc.y += v.y; acc.z += v.z; acc.w += v.w;
        }
    }
    float inv = 1.0f / fmaxf(g_deg[gh], 1.0f);
    float4 o = ((float4*)out)[(size_t)gh * 16 + l16];
    o.x += acc.x * inv; o.y += acc.y * inv;
    o.z += acc.z * inv; o.w += acc.w * inv;
    ((float4*)out)[(size_t)gh * 16 + l16] = o;
}

// ---------------------------------------------------------------------------
// Layer 1 via HMMA, 512 threads (PROVEN R14): h1 = relu(x@Ws1 + (nbr1/deg)@Wn1 + b1)
// ---------------------------------------------------------------------------
__global__ void __launch_bounds__(512)
gemm1_mma_kernel(const float* __restrict__ x,
                 const float* __restrict__ bias) {
    extern __shared__ char smem[];
    uint32_t smem_base = smem_to_u32(smem);
    int tid = threadIdx.x;
    int w = tid >> 5, l = tid & 31;
    int wm = w & 3, wn = w >> 2;

    {
        const uint32_t* hi32 = (const uint32_t*)g_B1hi;
        const uint32_t* lo32 = (const uint32_t*)g_B1lo;
        for (int i = tid; i < 32768; i += 512) {
            int kp = i & 63, n = (i >> 6) & 127, hilo = (i >> 13) & 1, ph = i >> 14;
            uint32_t v = (hilo ? lo32 : hi32)[ph * 8192 + n * 64 + kp];
            *(uint32_t*)(smem + SM_B + (ph * 2 + hilo) * TILE_B + n * RSTR + kp * 4) = v;
        }
    }

    int rowc = tid >> 2;
    int c0 = (tid & 3) << 5;

    const int nTiles = (NN + 127) / 128;
    for (int tile = blockIdx.x; tile < nTiles; tile += gridDim.x) {
        int base = tile * 128;
        float acc[2][4][4];
        #pragma unroll
        for (int bm = 0; bm < 2; bm++)
            #pragma unroll
            for (int bn = 0; bn < 4; bn++)
                #pragma unroll
                for (int j = 0; j < 4; j++) acc[bm][bn][j] = 0.f;

        #pragma unroll
        for (int ph = 0; ph < 2; ++ph) {
            __syncthreads();
            {
                const float* feat = ph ? g_nbr1 : x;
                int node = base + rowc;
                bool valid = node < NN;
                float scale = 1.0f;
                if (ph && valid) scale = 1.0f / fmaxf(g_deg[node], 1.0f);
                const float4* rp = (const float4*)(feat + (size_t)node * DI + c0);
                #pragma unroll
                for (int i = 0; i < 8; i++) {
                    float4 v = make_float4(0.f, 0.f, 0.f, 0.f);
                    if (valid) v = rp[i];
                    v.x *= scale; v.y *= scale; v.z *= scale; v.w *= scale;
                    int c = c0 + i * 4;
                    __nv_bfloat162 h01, l01, h23, l23;
                    h01.x = __float2bfloat16(v.x);
                    l01.x = __float2bfloat16(v.x - __bfloat162float(h01.x));
                    h01.y = __float2bfloat16(v.y);
                    l01.y = __float2bfloat16(v.y - __bfloat162float(h01.y));
                    h23.x = __float2bfloat16(v.z);
                    l23.x = __float2bfloat16(v.z - __bfloat162float(h23.x));
                    h23.y = __float2bfloat16(v.w);
                    l23.y = __float2bfloat16(v.w - __bfloat162float(h23.y));
                    uint32_t o = (uint32_t)(rowc * RSTR + c * 2);
                    *(__nv_bfloat162*)(smem + SM_A_HI + o)     = h01;
                    *(__nv_bfloat162*)(smem + SM_A_HI + o + 4) = h23;
                    *(__nv_bfloat162*)(smem + SM_A_LO + o)     = l01;
                    *(__nv_bfloat162*)(smem + SM_A_LO + o + 4) = l23;
                }
            }
            __syncthreads();

            uint32_t bb_hi = smem_base + SM_B + (uint32_t)(ph * 2) * TILE_B;
            #pragma unroll
            for (int s = 0; s < 8; s++) {
                int k0 = s << 4;
                uint32_t ahi[2][4], alo[2][4];
                #pragma unroll
                for (int bm = 0; bm < 2; bm++) {
                    int row = (wm << 5) + (bm << 4) + (l & 7) + (((l >> 3) & 1) << 3);
                    int col = k0 + ((l >> 4) << 3);
                    uint32_t ad = smem_base + (uint32_t)(row * RSTR + col * 2);
                    ldsm_x4(ahi[bm], ad + SM_A_HI);
                    ldsm_x4(alo[bm], ad + SM_A_LO);
                }
                uint32_t bhi[4][2], blo[4][2];
                #pragma unroll
                for (int t = 0; t < 2; t++) {
                    int row = (wn << 5) + (t << 4) + (l & 7) + ((l >> 4) << 3);
                    int col = k0 + (((l >> 3) & 1) << 3);
                    uint32_t bd = bb_hi + (uint32_t)(row * RSTR + col * 2);
                    uint32_t r[4];
                    ldsm_x4(r, bd);
                    bhi[2 * t][0] = r[0]; bhi[2 * t][1] = r[1];
                    bhi[2 * t + 1][0] = r[2]; bhi[2 * t + 1][1] = r[3];
                    ldsm_x4(r, bd + TILE_B);
                    blo[2 * t][0] = r[0]; blo[2 * t][1] = r[1];
                    blo[2 * t + 1][0] = r[2]; blo[2 * t + 1][1] = r[3];
                }
                #pragma unroll
                for (int bm = 0; bm < 2; bm++)
                    #pragma unroll
                    for (int bn = 0; bn < 4; bn++) {
                        mma_bf16(acc[bm][bn], ahi[bm], bhi[bn]);
                        mma_bf16(acc[bm][bn], ahi[bm], blo[bn]);
                        mma_bf16(acc[bm][bn], alo[bm], bhi[bn]);
                    }
            }
        }

        #pragma unroll
        for (int bm = 0; bm < 2; bm++) {
            int r0 = base + (wm << 5) + (bm << 4) + (l >> 2);
            #pragma unroll
            for (int bn = 0; bn < 4; bn++) {
                int n = (wn << 5) + (bn << 3) + ((l & 3) << 1);
                float2 bv = *(const float2*)(bias + n);
                #pragma unroll
                for (int half = 0; half < 2; half++) {
                    int r = r0 + half * 8;
                    if (r < NN) {
                        float o0 = fmaxf(acc[bm][bn][2 * half + 0] + bv.x, 0.f);
                        float o1 = fmaxf(acc[bm][bn][2 * half + 1] + bv.y, 0.f);
                        __nv_bfloat162 h2, l2;
                        h2.x = __float2bfloat16(o0);
                        l2.x = __float2bfloat16(o0 - __bfloat162float(h2.x));
                        h2.y = __float2bfloat16(o1);
                        l2.y = __float2bfloat16(o1 - __bfloat162float(h2.y));
                        *(__nv_bfloat162*)(g_h1hi + (size_t)r * DH + n) = h2;
                        *(__nv_bfloat162*)(g_h1lo + (size_t)r * DH + n) = l2;
                    }
                }
            }
        }
    }
}

// ---------------------------------------------------------------------------
// Layer 2 via HMMA, 512 threads, DOUBLE-BUFFERED A via cp.async:
//   N=128 GEMM, B2 = [Ws2 | Wn2]^T; cols 0-63 (+b2) -> d_out ; 64-127 -> g_p
// ---------------------------------------------------------------------------
__global__ void __launch_bounds__(512)
gemm2_mma_kernel(const float* __restrict__ bias,
                 float* __restrict__ out_ext) {
    extern __shared__ char smem[];
    uint32_t smem_base = smem_to_u32(smem);
    int tid = threadIdx.x;
    int w = tid >> 5, l = tid & 31;
    int wm = w & 3, wn = w >> 2;

    {   // preload B2 hi/lo
        const uint32_t* hi32 = (const uint32_t*)g_B2hi;
        const uint32_t* lo32 = (const uint32_t*)g_B2lo;
        for (int i = tid; i < 16384; i += 512) {
            int kp = i & 63, n = (i >> 6) & 127, hilo = i >> 13;
            uint32_t v = (hilo ? lo32 : hi32)[n * 64 + kp];
            *(uint32_t*)(smem + SM2_B + hilo * TILE_B + n * RSTR + kp * 4) = v;
        }
    }

    int rowc = tid >> 2;               // A-copy row (0..127)
    int jh = (tid & 3) << 4;           // uint32 quarter (16 of 64 per row)

    const int nTiles = (NN + 127) / 128;

    auto prefetch = [&](int tile, int p) {
        int node = tile * 128 + rowc;
        int sz = (node < NN) ? 16 : 0;
        const char* rh = (const char*)(g_h1hi + (size_t)node * DH) + jh * 4;
        const char* rl = (const char*)(g_h1lo + (size_t)node * DH) + jh * 4;
        uint32_t ob = smem_base + (uint32_t)(p * 2) * TILE_B
                    + (uint32_t)(rowc * RSTR + jh * 4);
        #pragma unroll
        for (int c = 0; c < 4; c++) {
            cp_async16(ob + c * 16, rh + c * 16, sz);
            cp_async16(ob + TILE_B + c * 16, rl + c * 16, sz);
        }
    };

    int p = 0;
    if (blockIdx.x < nTiles) prefetch(blockIdx.x, 0);
    CP_COMMIT();
    CP_WAIT0();
    __syncthreads();   // buf0 + B ready

    for (int tile = blockIdx.x; tile < nTiles; tile += gridDim.x) {
        int base = tile * 128;
        int nxt = tile + gridDim.x;
        if (nxt < nTiles) prefetch(nxt, p ^ 1);
        CP_COMMIT();

        float acc[2][4][4];
        #pragma unroll
        for (int bm = 0; bm < 2; bm++)
            #pragma unroll
            for (int bn = 0; bn < 4; bn++)
                #pragma unroll
                for (int j = 0; j < 4; j++) acc[bm][bn][j] = 0.f;

        uint32_t a_base = smem_base + (uint32_t)(p * 2) * TILE_B;
        uint32_t bb_hi = smem_base + SM2_B;
        #pragma unroll
        for (int s = 0; s < 8; s++) {
            int k0 = s << 4;
            uint32_t ahi[2][4], alo[2][4];
            #pragma unroll
            for (int bm = 0; bm < 2; bm++) {
                int row = (wm << 5) + (bm << 4) + (l & 7) + (((l >> 3) & 1) << 3);
                int col = k0 + ((l >> 4) << 3);
                uint32_t ad = a_base + (uint32_t)(row * RSTR + col * 2);
                ldsm_x4(ahi[bm], ad);
                ldsm_x4(alo[bm], ad + TILE_B);
            }
            uint32_t bhi[4][2], blo[4][2];
            #pragma unroll
            for (int t = 0; t < 2; t++) {
                int row = (wn << 5) + (t << 4) + (l & 7) + ((l >> 4) << 3);
                int col = k0 + (((l >> 3) & 1) << 3);
                uint32_t bd = bb_hi + (uint32_t)(row * RSTR + col * 2);
                uint32_t r[4];
                ldsm_x4(r, bd);
                bhi[2 * t][0] = r[0]; bhi[2 * t][1] = r[1];
                bhi[2 * t + 1][0] = r[2]; bhi[2 * t + 1][1] = r[3];
                ldsm_x4(r, bd + TILE_B);
                blo[2 * t][0] = r[0]; blo[2 * t][1] = r[1];
                blo[2 * t + 1][0] = r[2]; blo[2 * t + 1][1] = r[3];
            }
            #pragma unroll
            for (int bm = 0; bm < 2; bm++)
                #pragma unroll
                for (int bn = 0; bn < 4; bn++) {
                    mma_bf16(acc[bm][bn], ahi[bm], bhi[bn]);
                    mma_bf16(acc[bm][bn], ahi[bm], blo[bn]);
                    mma_bf16(acc[bm][bn], alo[bm], bhi[bn]);
                }
        }

        // Epilogue
        #pragma unroll
        for (int bm = 0; bm < 2; bm++) {
            int r0 = base + (wm << 5) + (bm << 4) + (l >> 2);
            #pragma unroll
            for (int bn = 0; bn < 4; bn++) {
                int n = (wn << 5) + (bn << 3) + ((l & 3) << 1);
                #pragma unroll
                for (int half = 0; half < 2; half++) {
                    int r = r0 + half * 8;
                    if (r < NN) {
                        float o0 = acc[bm][bn][2 * half + 0];
                        float o1 = acc[bm][bn][2 * half + 1];
                        if (n < 64) {
                            float2 bv = *(const float2*)(bias + n);
                            float2 o = make_float2(o0 + bv.x, o1 + bv.y);
                            *(float2*)(out_ext + (size_t)r * NC + n) = o;
                        } else {
                            float2 o = make_float2(o0, o1);
                            *(float2*)(g_p + (size_t)r * NC + (n - 64)) = o;
                        }
                    }
                }
            }
        }

        CP_WAIT0();
        __syncthreads();
        p ^= 1;
    }
}

// ---------------------------------------------------------------------------
extern "C" void kernel_launch(void* const* d_in, const int* in_sizes, int n_in,
                              void* d_out, int out_size) {
    const float* x    = (const float*)d_in[0];
    const int*   src  = (const int*)d_in[1];
    const int*   dst  = (const int*)d_in[2];
    const float* Ws1  = (const float*)d_in[3];
    const float* Wn1  = (const float*)d_in[4];
    const float* b1   = (const float*)d_in[5];
    const float* Ws2  = (const float*)d_in[6];
    const float* Wn2  = (const float*)d_in[7];
    const float* b2   = (const float*)d_in[8];
    float* out = (float*)d_out;

    cudaFuncSetAttribute(gemm1_mma_kernel, cudaFuncAttributeMaxDynamicSharedMemorySize, SMEM_MMA);
    cudaFuncSetAttribute(gemm2_mma_kernel, cudaFuncAttributeMaxDynamicSharedMemorySize, SMEM_MMA2);

    // 1) setup: zero cnt + convert weights (one kernel)
    setup_kernel<<<(49152 + NN + 255) / 256, 256>>>(Ws1, Wn1, Ws2, Wn2);
    // 2) CSR build
    hist_kernel<<<(NE + 255) / 256, 256>>>(dst);
    scan1_kernel<<<NBLK, 1024>>>();
    scan2_kernel<<<1, 128>>>();
    scan3_kernel<<<(NN + 255) / 256, 256>>>();
    fill_kernel<<<(NE + 255) / 256, 256>>>(src, dst);
    // 3) layer-1 gather (standalone, high occupancy) + GEMM
    gather1_kernel<<<(NN * 32 + 255) / 256, 256>>>(x);
    gemm1_mma_kernel<<<148, 512, SMEM_MMA>>>(x, b1);
    // 4) layer-2 dual GEMM (double-buffered A): d_out = h1@Ws2 + b2 ; g_p = h1@Wn2
    gemm2_mma_kernel<<<148, 512, SMEM_MMA2>>>(b2, out);
    // 5) gather of g_p fused with final add
    gather2_kernel<<<(NN * 16 + 255) / 256, 256>>>(out);
}

// round 17
// speedup vs baseline: 1.5819x; 1.0723x over previous
#include <cuda_runtime.h>
#include <cuda_bf16.h>
#include <cstdint>
#include <stdint.h>

#define NN 100000
#define NE 600000
#define DI 128
#define DH 128
#define NC 64
#define NBLK 98          // ceil(NN/1024)

// Scratch (device globals -- referenced ONLY inside kernels, never from host)
__device__ __align__(16) float g_nbr1[(size_t)NN * DI];   // layer-1 neighbor sums
__device__ __align__(16) float g_p[(size_t)NN * NC];      // h1 @ Wn2 (pre-projected)
__device__ float g_deg[NN];                               // in-degree (float)
// CSR (rebuilt every call)
__device__ int g_cnt[NN];
__device__ int g_rowptr[NN];
__device__ int g_cursor[NN];
__device__ int g_eidx[NE];
__device__ int g_blksum[128];
// h1 stored directly as bf16 hi/lo (written by gemm1 epilogue)
__device__ __align__(16) __nv_bfloat16 g_h1hi[(size_t)NN * DH];
__device__ __align__(16) __nv_bfloat16 g_h1lo[(size_t)NN * DH];
// Pre-converted layer-1 weights, B[n][k] = W[k][n], bf16 hi/lo, [ph][128n][128k]
__device__ __align__(16) __nv_bfloat16 g_B1hi[2 * 128 * 128];
__device__ __align__(16) __nv_bfloat16 g_B1lo[2 * 128 * 128];
// Pre-converted layer-2 weights: B2[n][k]; n<64 -> Ws2 col n, n>=64 -> Wn2 col n-64
__device__ __align__(16) __nv_bfloat16 g_B2hi[128 * 128];
__device__ __align__(16) __nv_bfloat16 g_B2lo[128 * 128];

// ---------------- HMMA helpers (baseline PTX, sm_80+, no 'a' target) ----
__device__ __forceinline__ uint32_t smem_to_u32(const void* p) {
    uint32_t a;
    asm("{ .reg .u64 t; cvta.to.shared.u64 t, %1; cvt.u32.u64 %0, t; }" : "=r"(a) : "l"(p));
    return a;
}
__device__ __forceinline__ void ldsm_x4(uint32_t* r, uint32_t addr) {
    asm volatile("ldmatrix.sync.aligned.m8n8.x4.shared.b16 {%0,%1,%2,%3}, [%4];"
                 : "=r"(r[0]), "=r"(r[1]), "=r"(r[2]), "=r"(r[3]) : "r"(addr));
}
__device__ __forceinline__ void mma_bf16(float* d, const uint32_t* a, const uint32_t* b) {
    asm volatile("mma.sync.aligned.m16n8k16.row.col.f32.bf16.bf16.f32 "
                 "{%0,%1,%2,%3}, {%4,%5,%6,%7}, {%8,%9}, {%0,%1,%2,%3};"
                 : "+f"(d[0]), "+f"(d[1]), "+f"(d[2]), "+f"(d[3])
                 : "r"(a[0]), "r"(a[1]), "r"(a[2]), "r"(a[3]), "r"(b[0]), "r"(b[1]));
}
__device__ __forceinline__ void cp_async16(uint32_t saddr, const void* g, int szbytes) {
    asm volatile("cp.async.cg.shared.global [%0], [%1], 16, %2;"
                 :: "r"(saddr), "l"(g), "r"(szbytes));
}
#define CP_COMMIT() asm volatile("cp.async.commit_group;" ::: "memory")
#define CP_WAIT0()  asm volatile("cp.async.wait_group 0;" ::: "memory")

// SMEM maps: rows padded to 136 bf16 (272B) -> conflict-free ldsm
#define RSTR 272
#define TILE_B (128 * RSTR)
// gemm1: A_hi, A_lo, then 4 B tiles [ph][hi/lo]
#define SM_A_HI 0
#define SM_A_LO TILE_B
#define SM_B    (2 * TILE_B)
#define SMEM_MMA (6 * TILE_B)      // 208896 B
// gemm2: A0hi, A0lo, A1hi, A1lo, B_hi, B_lo
#define SM2_B   (4 * TILE_B)
#define SMEM_MMA2 (6 * TILE_B)     // 208896 B

// ================= setup: zero cnt + convert weights =================
__global__ void setup_kernel(const float* __restrict__ Ws1, const float* __restrict__ Wn1,
                             const float* __restrict__ Ws2, const float* __restrict__ Wn2) {
    int i = blockIdx.x * blockDim.x + threadIdx.x;
    if (i < 32768) {                       // W1: [ph][n][k]
        int ph = i >> 14, rem = i & 16383;
        int n = rem >> 7, k = rem & 127;
        const float* W = ph ? Wn1 : Ws1;
        float v = W[k * 128 + n];
        __nv_bfloat16 h = __float2bfloat16(v);
        g_B1hi[i] = h;
        g_B1lo[i] = __float2bfloat16(v - __bfloat162float(h));
    } else if (i < 49152) {                // W2: [n][k], n<64 Ws2 else Wn2
        int j = i - 32768;
        int n = j >> 7, k = j & 127;
        float v = (n < 64) ? Ws2[k * 64 + n] : Wn2[k * 64 + (n - 64)];
        __nv_bfloat16 h = __float2bfloat16(v);
        g_B2hi[j] = h;
        g_B2lo[j] = __float2bfloat16(v - __bfloat162float(h));
    } else if (i < 49152 + NN) {
        g_cnt[i - 49152] = 0;
    }
}

// ================= CSR build (proven R14) =================
__global__ void hist_kernel(const int* __restrict__ dst) {
    int e = blockIdx.x * blockDim.x + threadIdx.x;
    if (e < NE) atomicAdd(&g_cnt[__ldg(dst + e)], 1);
}
__global__ void scan1_kernel() {
    __shared__ int s[1024];
    int t = threadIdx.x;
    int idx = blockIdx.x * 1024 + t;
    int v = (idx < NN) ? g_cnt[idx] : 0;
    s[t] = v;
    __syncthreads();
    for (int off = 1; off < 1024; off <<= 1) {
        int tmp = (t >= off) ? s[t - off] : 0;
        __syncthreads();
        s[t] += tmp;
        __syncthreads();
    }
    if (idx < NN) g_rowptr[idx] = s[t] - v;
    if (t == 1023) g_blksum[blockIdx.x] = s[t];
}
__global__ void scan2_kernel() {
    __shared__ int s[128];
    int t = threadIdx.x;
    int v = (t < NBLK) ? g_blksum[t] : 0;
    s[t] = v;
    __syncthreads();
    for (int off = 1; off < 128; off <<= 1) {
        int tmp = (t >= off) ? s[t - off] : 0;
        __syncthreads();
        s[t] += tmp;
        __syncthreads();
    }
    if (t < NBLK) g_blksum[t] = s[t] - v;
}
__global__ void scan3_kernel() {
    int i = blockIdx.x * blockDim.x + threadIdx.x;
    if (i >= NN) return;
    int rp = g_rowptr[i] + g_blksum[i >> 10];
    g_rowptr[i] = rp;
    g_cursor[i] = rp;
    g_deg[i] = (float)g_cnt[i];
}
__global__ void fill_kernel(const int* __restrict__ src, const int* __restrict__ dst) {
    int e = blockIdx.x * blockDim.x + threadIdx.x;
    if (e < NE) {
        int d = __ldg(dst + e);
        int pos = atomicAdd(&g_cursor[d], 1);
        g_eidx[pos] = __ldg(src + e);
    }
}

// ================= Gathers (proven R14) =================
__global__ void gather1_kernel(const float* __restrict__ x) {
    int gw = (blockIdx.x * blockDim.x + threadIdx.x) >> 5;
    if (gw >= NN) return;
    int lane = threadIdx.x & 31;
    int beg = __ldg(g_rowptr + gw);
    int cnt = __ldg(g_cnt + gw);
    float4 acc = make_float4(0.f, 0.f, 0.f, 0.f);
    for (int i0 = 0; i0 < cnt; i0 += 32) {
        int m = min(32, cnt - i0);
        int myidx = (lane < m) ? __ldg(g_eidx + beg + i0 + lane) : 0;
        for (int j = 0; j < m; j++) {
            int s = __shfl_sync(0xffffffffu, myidx, j);
            float4 v = __ldg((const float4*)x + (size_t)s * 32 + lane);
            acc.x += v.x; acc.y += v.y; acc.z += v.z; acc.w += v.w;
        }
    }
    ((float4*)g_nbr1)[(size_t)gw * 32 + lane] = acc;
}

__global__ void gather2_kernel(float* __restrict__ out) {
    int gh = (blockIdx.x * blockDim.x + threadIdx.x) >> 4;
    if (gh >= NN) return;
    int l16 = threadIdx.x & 15;
    unsigned mask = 0xFFFFu << (threadIdx.x & 16);
    int beg = __ldg(g_rowptr + gh);
    int cnt = __ldg(g_cnt + gh);
    float4 acc = make_float4(0.f, 0.f, 0.f, 0.f);
    for (int i0 = 0; i0 < cnt; i0 += 16) {
        int m = min(16, cnt - i0);
        int myidx = (l16 < m) ? __ldg(g_eidx + beg + i0 + l16) : 0;
        for (int j = 0; j < m; j++) {
            int s = __shfl_sync(mask, myidx, j, 16);
            float4 v = __ldg((const float4*)g_p + (size_t)s * 16 + l16);
            acc.x += v.x; acc.y += v.y; acc.z += v.z; acc.w += v.w;
        }
    }
    float inv = 1.0f / fmaxf(g_deg[gh], 1.0f);
    float4 o = ((float4*)out)[(size_t)gh * 16 + l16];
    o.x += acc.x * inv; o.y += acc.y * inv;
    o.z += acc.z * inv; o.w += acc.w * inv;
    ((float4*)out)[(size_t)gh * 16 + l16] = o;
}

// ---------------------------------------------------------------------------
// Layer 1 via HMMA, 512 threads, REGISTER-PIPELINED A loads:
//   h1 = relu(x@Ws1 + (nbr1/deg)@Wn1 + b1) -> g_h1hi/g_h1lo (bf16 split)
// Next phase's/tile's fp32 A fragment is LDG'd into regs while MMA runs.
// ---------------------------------------------------------------------------
__global__ void __launch_bounds__(512)
gemm1_mma_kernel(const float* __restrict__ x,
                 const float* __restrict__ bias) {
    extern __shared__ char smem[];
    uint32_t smem_base = smem_to_u32(smem);
    int tid = threadIdx.x;
    int w = tid >> 5, l = tid & 31;
    int wm = w & 3, wn = w >> 2;

    {
        const uint32_t* hi32 = (const uint32_t*)g_B1hi;
        const uint32_t* lo32 = (const uint32_t*)g_B1lo;
        for (int i = tid; i < 32768; i += 512) {
            int kp = i & 63, n = (i >> 6) & 127, hilo = (i >> 13) & 1, ph = i >> 14;
            uint32_t v = (hilo ? lo32 : hi32)[ph * 8192 + n * 64 + kp];
            *(uint32_t*)(smem + SM_B + (ph * 2 + hilo) * TILE_B + n * RSTR + kp * 4) = v;
        }
    }

    int rowc = tid >> 2;               // loader row (0..127)
    int c0 = (tid & 3) << 5;           // feature quarter

    // register A fragment loader
    float4 v[8];
    float scale;
    auto ldreg = [&](int ph, int base) {
        const float* feat = ph ? g_nbr1 : x;
        int node = base + rowc;
        bool valid = node < NN;
        scale = 1.0f;
        if (ph && valid) scale = 1.0f / fmaxf(g_deg[node], 1.0f);
        const float4* rp = (const float4*)(feat + (size_t)node * DI + c0);
        #pragma unroll
        for (int i = 0; i < 8; i++)
            v[i] = valid ? __ldg(rp + i) : make_float4(0.f, 0.f, 0.f, 0.f);
    };

    const int nTiles = (NN + 127) / 128;
    if (blockIdx.x < nTiles) ldreg(0, blockIdx.x * 128);

    for (int tile = blockIdx.x; tile < nTiles; tile += gridDim.x) {
        int base = tile * 128;
        float acc[2][4][4];
        #pragma unroll
        for (int bm = 0; bm < 2; bm++)
            #pragma unroll
            for (int bn = 0; bn < 4; bn++)
                #pragma unroll
                for (int j = 0; j < 4; j++) acc[bm][bn][j] = 0.f;

        #pragma unroll
        for (int ph = 0; ph < 2; ++ph) {
            __syncthreads();   // prev MMA readers done with A buffers
            {   // convert regs -> bf16 hi/lo, swizzled STS
                float sc = scale;
                #pragma unroll
                for (int i = 0; i < 8; i++) {
                    float4 t = v[i];
                    t.x *= sc; t.y *= sc; t.z *= sc; t.w *= sc;
                    int c = c0 + i * 4;
                    __nv_bfloat162 h01, l01, h23, l23;
                    h01.x = __float2bfloat16(t.x);
                    l01.x = __float2bfloat16(t.x - __bfloat162float(h01.x));
                    h01.y = __float2bfloat16(t.y);
                    l01.y = __float2bfloat16(t.y - __bfloat162float(h01.y));
                    h23.x = __float2bfloat16(t.z);
                    l23.x = __float2bfloat16(t.z - __bfloat162float(h23.x));
                    h23.y = __float2bfloat16(t.w);
                    l23.y = __float2bfloat16(t.w - __bfloat162float(h23.y));
                    uint32_t o = (uint32_t)(rowc * RSTR + c * 2);
                    *(__nv_bfloat162*)(smem + SM_A_HI + o)     = h01;
                    *(__nv_bfloat162*)(smem + SM_A_HI + o + 4) = h23;
                    *(__nv_bfloat162*)(smem + SM_A_LO + o)     = l01;
                    *(__nv_bfloat162*)(smem + SM_A_LO + o + 4) = l23;
                }
            }
            // prefetch next A fragment (overlaps with MMA below)
            if (ph == 0) {
                ldreg(1, base);
            } else {
                int nt = tile + gridDim.x;
                if (nt < nTiles) ldreg(0, nt * 128);
            }
            __syncthreads();

            uint32_t bb_hi = smem_base + SM_B + (uint32_t)(ph * 2) * TILE_B;
            #pragma unroll
            for (int s = 0; s < 8; s++) {
                int k0 = s << 4;
                uint32_t ahi[2][4], alo[2][4];
                #pragma unroll
                for (int bm = 0; bm < 2; bm++) {
                    int row = (wm << 5) + (bm << 4) + (l & 7) + (((l >> 3) & 1) << 3);
                    int col = k0 + ((l >> 4) << 3);
                    uint32_t ad = smem_base + (uint32_t)(row * RSTR + col * 2);
                    ldsm_x4(ahi[bm], ad + SM_A_HI);
                    ldsm_x4(alo[bm], ad + SM_A_LO);
                }
                uint32_t bhi[4][2], blo[4][2];
                #pragma unroll
                for (int t = 0; t < 2; t++) {
                    int row = (wn << 5) + (t << 4) + (l & 7) + ((l >> 4) << 3);
                    int col = k0 + (((l >> 3) & 1) << 3);
                    uint32_t bd = bb_hi + (uint32_t)(row * RSTR + col * 2);
                    uint32_t r[4];
                    ldsm_x4(r, bd);
                    bhi[2 * t][0] = r[0]; bhi[2 * t][1] = r[1];
                    bhi[2 * t + 1][0] = r[2]; bhi[2 * t + 1][1] = r[3];
                    ldsm_x4(r, bd + TILE_B);
                    blo[2 * t][0] = r[0]; blo[2 * t][1] = r[1];
                    blo[2 * t + 1][0] = r[2]; blo[2 * t + 1][1] = r[3];
                }
                #pragma unroll
                for (int bm = 0; bm < 2; bm++)
                    #pragma unroll
                    for (int bn = 0; bn < 4; bn++) {
                        mma_bf16(acc[bm][bn], ahi[bm], bhi[bn]);
                        mma_bf16(acc[bm][bn], ahi[bm], blo[bn]);
                        mma_bf16(acc[bm][bn], alo[bm], bhi[bn]);
                    }
            }
        }

        // Epilogue: bias + relu -> g_h1hi/g_h1lo
        #pragma unroll
        for (int bm = 0; bm < 2; bm++) {
            int r0 = base + (wm << 5) + (bm << 4) + (l >> 2);
            #pragma unroll
            for (int bn = 0; bn < 4; bn++) {
                int n = (wn << 5) + (bn << 3) + ((l & 3) << 1);
                float2 bv = *(const float2*)(bias + n);
                #pragma unroll
                for (int half = 0; half < 2; half++) {
                    int r = r0 + half * 8;
                    if (r < NN) {
                        float o0 = fmaxf(acc[bm][bn][2 * half + 0] + bv.x, 0.f);
                        float o1 = fmaxf(acc[bm][bn][2 * half + 1] + bv.y, 0.f);
                        __nv_bfloat162 h2, l2;
                        h2.x = __float2bfloat16(o0);
                        l2.x = __float2bfloat16(o0 - __bfloat162float(h2.x));
                        h2.y = __float2bfloat16(o1);
                        l2.y = __float2bfloat16(o1 - __bfloat162float(h2.y));
                        *(__nv_bfloat162*)(g_h1hi + (size_t)r * DH + n) = h2;
                        *(__nv_bfloat162*)(g_h1lo + (size_t)r * DH + n) = l2;
                    }
                }
            }
        }
    }
}

// ---------------------------------------------------------------------------
// Layer 2 via HMMA, 512 threads, DOUBLE-BUFFERED A via cp.async (PROVEN R16)
// ---------------------------------------------------------------------------
__global__ void __launch_bounds__(512)
gemm2_mma_kernel(const float* __restrict__ bias,
                 float* __restrict__ out_ext) {
    extern __shared__ char smem[];
    uint32_t smem_base = smem_to_u32(smem);
    int tid = threadIdx.x;
    int w = tid >> 5, l = tid & 31;
    int wm = w & 3, wn = w >> 2;

    {   // preload B2 hi/lo
        const uint32_t* hi32 = (const uint32_t*)g_B2hi;
        const uint32_t* lo32 = (const uint32_t*)g_B2lo;
        for (int i = tid; i < 16384; i += 512) {
            int kp = i & 63, n = (i >> 6) & 127, hilo = i >> 13;
            uint32_t v = (hilo ? lo32 : hi32)[n * 64 + kp];
            *(uint32_t*)(smem + SM2_B + hilo * TILE_B + n * RSTR + kp * 4) = v;
        }
    }

    int rowc = tid >> 2;               // A-copy row (0..127)
    int jh = (tid & 3) << 4;           // uint32 quarter (16 of 64 per row)

    const int nTiles = (NN + 127) / 128;

    auto prefetch = [&](int tile, int p) {
        int node = tile * 128 + rowc;
        int sz = (node < NN) ? 16 : 0;
        const char* rh = (const char*)(g_h1hi + (size_t)node * DH) + jh * 4;
        const char* rl = (const char*)(g_h1lo + (size_t)node * DH) + jh * 4;
        uint32_t ob = smem_base + (uint32_t)(p * 2) * TILE_B
                    + (uint32_t)(rowc * RSTR + jh * 4);
        #pragma unroll
        for (int c = 0; c < 4; c++) {
            cp_async16(ob + c * 16, rh + c * 16, sz);
            cp_async16(ob + TILE_B + c * 16, rl + c * 16, sz);
        }
    };

    int p = 0;
    if (blockIdx.x < nTiles) prefetch(blockIdx.x, 0);
    CP_COMMIT();
    CP_WAIT0();
    __syncthreads();   // buf0 + B ready

    for (int tile = blockIdx.x; tile < nTiles; tile += gridDim.x) {
        int base = tile * 128;
        int nxt = tile + gridDim.x;
        if (nxt < nTiles) prefetch(nxt, p ^ 1);
        CP_COMMIT();

        float acc[2][4][4];
        #pragma unroll
        for (int bm = 0; bm < 2; bm++)
            #pragma unroll
            for (int bn = 0; bn < 4; bn++)
                #pragma unroll
                for (int j = 0; j < 4; j++) acc[bm][bn][j] = 0.f;

        uint32_t a_base = smem_base + (uint32_t)(p * 2) * TILE_B;
        uint32_t bb_hi = smem_base + SM2_B;
        #pragma unroll
        for (int s = 0; s < 8; s++) {
            int k0 = s << 4;
            uint32_t ahi[2][4], alo[2][4];
            #pragma unroll
            for (int bm = 0; bm < 2; bm++) {
                int row = (wm << 5) + (bm << 4) + (l & 7) + (((l >> 3) & 1) << 3);
                int col = k0 + ((l >> 4) << 3);
                uint32_t ad = a_base + (uint32_t)(row * RSTR + col * 2);
                ldsm_x4(ahi[bm], ad);
                ldsm_x4(alo[bm], ad + TILE_B);
            }
            uint32_t bhi[4][2], blo[4][2];
            #pragma unroll
            for (int t = 0; t < 2; t++) {
                int row = (wn << 5) + (t << 4) + (l & 7) + ((l >> 4) << 3);
                int col = k0 + (((l >> 3) & 1) << 3);
                uint32_t bd = bb_hi + (uint32_t)(row * RSTR + col * 2);
                uint32_t r[4];
                ldsm_x4(r, bd);
                bhi[2 * t][0] = r[0]; bhi[2 * t][1] = r[1];
                bhi[2 * t + 1][0] = r[2]; bhi[2 * t + 1][1] = r[3];
                ldsm_x4(r, bd + TILE_B);
                blo[2 * t][0] = r[0]; blo[2 * t][1] = r[1];
                blo[2 * t + 1][0] = r[2]; blo[2 * t + 1][1] = r[3];
            }
            #pragma unroll
            for (int bm = 0; bm < 2; bm++)
                #pragma unroll
                for (int bn = 0; bn < 4; bn++) {
                    mma_bf16(acc[bm][bn], ahi[bm], bhi[bn]);
                    mma_bf16(acc[bm][bn], ahi[bm], blo[bn]);
                    mma_bf16(acc[bm][bn], alo[bm], bhi[bn]);
                }
        }

        // Epilogue
        #pragma unroll
        for (int bm = 0; bm < 2; bm++) {
            int r0 = base + (wm << 5) + (bm << 4) + (l >> 2);
            #pragma unroll
            for (int bn = 0; bn < 4; bn++) {
                int n = (wn << 5) + (bn << 3) + ((l & 3) << 1);
                #pragma unroll
                for (int half = 0; half < 2; half++) {
                    int r = r0 + half * 8;
                    if (r < NN) {
                        float o0 = acc[bm][bn][2 * half + 0];
                        float o1 = acc[bm][bn][2 * half + 1];
                        if (n < 64) {
                            float2 bv = *(const float2*)(bias + n);
                            float2 o = make_float2(o0 + bv.x, o1 + bv.y);
                            *(float2*)(out_ext + (size_t)r * NC + n) = o;
                        } else {
                            float2 o = make_float2(o0, o1);
                            *(float2*)(g_p + (size_t)r * NC + (n - 64)) = o;
                        }
                    }
                }
            }
        }

        CP_WAIT0();
        __syncthreads();
        p ^= 1;
    }
}

// ---------------------------------------------------------------------------
extern "C" void kernel_launch(void* const* d_in, const int* in_sizes, int n_in,
                              void* d_out, int out_size) {
    const float* x    = (const float*)d_in[0];
    const int*   src  = (const int*)d_in[1];
    const int*   dst  = (const int*)d_in[2];
    const float* Ws1  = (const float*)d_in[3];
    const float* Wn1  = (const float*)d_in[4];
    const float* b1   = (const float*)d_in[5];
    const float* Ws2  = (const float*)d_in[6];
    const float* Wn2  = (const float*)d_in[7];
    const float* b2   = (const float*)d_in[8];
    float* out = (float*)d_out;

    cudaFuncSetAttribute(gemm1_mma_kernel, cudaFuncAttributeMaxDynamicSharedMemorySize, SMEM_MMA);
    cudaFuncSetAttribute(gemm2_mma_kernel, cudaFuncAttributeMaxDynamicSharedMemorySize, SMEM_MMA2);

    // 1) setup: zero cnt + convert weights (one kernel)
    setup_kernel<<<(49152 + NN + 255) / 256, 256>>>(Ws1, Wn1, Ws2, Wn2);
    // 2) CSR build
    hist_kernel<<<(NE + 255) / 256, 256>>>(dst);
    scan1_kernel<<<NBLK, 1024>>>();
    scan2_kernel<<<1, 128>>>();
    scan3_kernel<<<(NN + 255) / 256, 256>>>();
    fill_kernel<<<(NE + 255) / 256, 256>>>(src, dst);
    // 3) layer-1 gather + register-pipelined GEMM
    gather1_kernel<<<(NN * 32 + 255) / 256, 256>>>(x);
    gemm1_mma_kernel<<<148, 512, SMEM_MMA>>>(x, b1);
    // 4) layer-2 dual GEMM (double-buffered A): d_out = h1@Ws2 + b2 ; g_p = h1@Wn2
    gemm2_mma_kernel<<<148, 512, SMEM_MMA2>>>(b2, out);
    // 5) gather of g_p fused with final add
    gather2_kernel<<<(NN * 16 + 255) / 256, 256>>>(out);
}